// round 7
// baseline (speedup 1.0000x reference)
#include <cuda_runtime.h>

#define SS   21      // search size
#define PAD  10
#define BS   4       // block size
#define TILE 24      // BS + SS - 1
#define TP   28      // tile pitch in floats
#define H    256
#define W    256

__global__ __launch_bounds__(96)
void pred_kernel(const float* __restrict__ im1,
                 const float* __restrict__ im2,
                 float* __restrict__ out)
{
    __shared__ __align__(16) float im2t[TILE * TP];
    __shared__ float im1t[16];
    __shared__ float red_f[16];     // final weighted sums (atomic accumulate)
    __shared__ float s_wsum;        // softmax normalizer (atomic accumulate)
    __shared__ int   s_min_i;       // CTA min of vol, as ordered int bits

    const int t  = threadIdx.x;
    const int bx = blockIdx.x, by = blockIdx.y, b = blockIdx.z;
    const float* i1 = im1 + b * H * W;
    const float* i2 = im2 + b * H * W;

    const int x0 = bx * BS - PAD;
    const int y0 = by * BS - PAD;

    // ---- Phase 0: load 24x24 im2 halo tile + init accumulators ----
    if (bx >= 3 && bx <= 60 && by >= 3 && by <= 60) {
        // interior fast path: coalesced float2 (x0 even => 8B aligned)
        const int row = t / 12;          // 0..7
        const int c2  = t - row * 12;    // 0..11
        #pragma unroll
        for (int p = 0; p < 3; p++) {
            int r = row + p * 8;
            float2 v = *(const float2*)(i2 + (y0 + r) * W + x0 + c2 * 2);
            *(float2*)&im2t[r * TP + c2 * 2] = v;
        }
    } else {
        // border path: predicated zero-pad, coalesced scalar
        #pragma unroll
        for (int q = 0; q < 6; q++) {
            int idx = t + q * 96;
            int r = idx / TILE, c = idx - r * TILE;
            int y = y0 + r, x = x0 + c;
            float v = 0.0f;
            if ((unsigned)y < (unsigned)H && (unsigned)x < (unsigned)W)
                v = i2[y * W + x];
            im2t[r * TP + c] = v;
        }
    }
    if (t < 16) {
        int py = t >> 2, px = t & 3;
        im1t[t] = i1[(by * BS + py) * W + bx * BS + px];
        red_f[t] = 0.0f;
    } else if (t == 16) {
        s_min_i = 0x7f7fffff;   // FLT_MAX bits
    } else if (t == 17) {
        s_wsum = 0.0f;
    }
    __syncthreads();

    // ---- mapping: t = 4*i + py (py in adjacent lanes) ----
    const int i  = t >> 2;          // shift row 0..20
    const int py = t & 3;           // pixel row 0..3
    const bool act = (t < 84);
    const unsigned gmask = (t >= 64) ? 0x000FFFFFu : 0xFFFFFFFFu;

    float r[TILE];                  // register-resident im2 row (py+i)
    float vol[SS];

    if (act) {
        const float4* rp = (const float4*)&im2t[(py + i) * TP];
        #pragma unroll
        for (int q = 0; q < 6; q++) {
            float4 v = rp[q];
            r[q * 4 + 0] = v.x; r[q * 4 + 1] = v.y;
            r[q * 4 + 2] = v.z; r[q * 4 + 3] = v.w;
        }
        const float a0 = im1t[py * 4 + 0], a1 = im1t[py * 4 + 1];
        const float a2 = im1t[py * 4 + 2], a3 = im1t[py * 4 + 3];

        #pragma unroll
        for (int j = 0; j < SS; j++) {
            vol[j] = fabsf(a0 - r[j])     + fabsf(a1 - r[j + 1])
                   + fabsf(a2 - r[j + 2]) + fabsf(a3 - r[j + 3]);
        }
        // allreduce over py within 4-lane group
        #pragma unroll
        for (int j = 0; j < SS; j++) {
            vol[j] += __shfl_xor_sync(gmask, vol[j], 1);
            vol[j] += __shfl_xor_sync(gmask, vol[j], 2);
        }
        float lmin = vol[0];
        #pragma unroll
        for (int j = 1; j < SS; j++) lmin = fminf(lmin, vol[j]);
        // vol >= 0, so int compare of float bits == float compare
        if (py == 0) atomicMin(&s_min_i, __float_as_int(lmin));
    }
    __syncthreads();

    // ---- Phase 3: fused weights + weighted accumulation ----
    if (act) {
        // w = exp(-6.25*(vol - vmin)) = 2^(K*vol + M), K = -6.25*log2(e)
        const float K = -9.016844005555897f;
        const float M = -K * __int_as_float(s_min_i);
        float lsum = 0.0f;
        float acc0 = 0.f, acc1 = 0.f, acc2 = 0.f, acc3 = 0.f;
        #pragma unroll
        for (int j = 0; j < SS; j++) {
            float e = fmaf(vol[j], K, M);
            float wv;
            asm("ex2.approx.ftz.f32 %0, %1;" : "=f"(wv) : "f"(e));
            lsum += wv;
            acc0 = fmaf(wv, r[j],     acc0);
            acc1 = fmaf(wv, r[j + 1], acc1);
            acc2 = fmaf(wv, r[j + 2], acc2);
            acc3 = fmaf(wv, r[j + 3], acc3);
        }
        if (py == 0) atomicAdd(&s_wsum, lsum);
        const int pb = py * 4;
        atomicAdd(&red_f[pb + 0], acc0);
        atomicAdd(&red_f[pb + 1], acc1);
        atomicAdd(&red_f[pb + 2], acc2);
        atomicAdd(&red_f[pb + 3], acc3);
    }
    __syncthreads();

    // ---- Phase 4: normalize, store ----
    if (t < 16) {
        int py2 = t >> 2, px2 = t & 3;
        out[b * H * W + (by * BS + py2) * W + bx * BS + px2]
            = red_f[t] / s_wsum;
    }
}

extern "C" void kernel_launch(void* const* d_in, const int* in_sizes, int n_in,
                              void* d_out, int out_size) {
    const float* im1 = (const float*)d_in[0];
    const float* im2 = (const float*)d_in[1];
    float* out = (float*)d_out;
    dim3 grid(W / BS, H / BS, 2);   // (64, 64, 2)
    pred_kernel<<<grid, 96>>>(im1, im2, out);
}

// round 8
// speedup vs baseline: 1.6024x; 1.6024x over previous
#include <cuda_runtime.h>

#define SS   21      // search size
#define PAD  10
#define BS   4       // block size
#define TILE 24      // BS + SS - 1
#define TP   28      // tile pitch in floats
#define H    256
#define W    256

__global__ __launch_bounds__(96, 14)
void pred_kernel(const float* __restrict__ im1,
                 const float* __restrict__ im2,
                 float* __restrict__ out)
{
    __shared__ __align__(16) float im2t[TILE * TP];
    __shared__ float im1t[16];
    __shared__ float red[16][21];   // per-pixel partial weighted sums over i
    __shared__ float sg[21];        // per-i group min, then per-i weight-sum
    __shared__ float s_min;

    const int t  = threadIdx.x;
    const int bx = blockIdx.x, by = blockIdx.y, b = blockIdx.z;
    const float* i1 = im1 + b * H * W;
    const float* i2 = im2 + b * H * W;

    const int x0 = bx * BS - PAD;
    const int y0 = by * BS - PAD;

    // ---- Phase 0: load 24x24 im2 halo tile ----
    if (bx >= 3 && bx <= 60 && by >= 3 && by <= 60) {
        const int row = t / 12;          // 0..7
        const int c2  = t - row * 12;    // 0..11
        #pragma unroll
        for (int p = 0; p < 3; p++) {
            int r = row + p * 8;
            float2 v = *(const float2*)(i2 + (y0 + r) * W + x0 + c2 * 2);
            *(float2*)&im2t[r * TP + c2 * 2] = v;
        }
    } else {
        #pragma unroll
        for (int q = 0; q < 6; q++) {
            int idx = t + q * 96;
            int r = idx / TILE, c = idx - r * TILE;
            int y = y0 + r, x = x0 + c;
            float v = 0.0f;
            if ((unsigned)y < (unsigned)H && (unsigned)x < (unsigned)W)
                v = i2[y * W + x];
            im2t[r * TP + c] = v;
        }
    }
    if (t < 16) {
        int py = t >> 2, px = t & 3;
        im1t[t] = i1[(by * BS + py) * W + bx * BS + px];
    }
    __syncthreads();

    // ---- mapping: t = 4*i + py (py in adjacent lanes) ----
    const int i  = t >> 2;          // shift row 0..20
    const int py = t & 3;           // pixel row 0..3
    const bool act = (t < 84);
    const unsigned gmask = (t >= 64) ? 0x000FFFFFu : 0xFFFFFFFFu;

    const unsigned sb = (unsigned)__cvta_generic_to_shared(&im2t[(py + i) * TP]);
    float vol[SS];

    // ---- Phase 1: SADs with sliding-window row loads (only ~8 r live) ----
    if (act) {
        const float a0 = im1t[py * 4 + 0], a1 = im1t[py * 4 + 1];
        const float a2 = im1t[py * 4 + 2], a3 = im1t[py * 4 + 3];
        float r[TILE];
        #pragma unroll
        for (int g = 0; g < 6; g++) {
            float4 v = ((const float4*)__cvta_shared_to_generic((size_t)sb))[g];
            r[4*g] = v.x; r[4*g+1] = v.y; r[4*g+2] = v.z; r[4*g+3] = v.w;
            if (g >= 1) {
                #pragma unroll
                for (int jj = 0; jj < 4; jj++) {
                    int j = 4 * (g - 1) + jj;
                    vol[j] = fabsf(a0 - r[j])     + fabsf(a1 - r[j + 1])
                           + fabsf(a2 - r[j + 2]) + fabsf(a3 - r[j + 3]);
                }
            }
        }
        vol[20] = fabsf(a0 - r[20]) + fabsf(a1 - r[21])
                + fabsf(a2 - r[22]) + fabsf(a3 - r[23]);

        // allreduce over py within 4-lane group
        #pragma unroll
        for (int j = 0; j < SS; j++) {
            vol[j] += __shfl_xor_sync(gmask, vol[j], 1);
            vol[j] += __shfl_xor_sync(gmask, vol[j], 2);
        }
        float lmin = vol[0];
        #pragma unroll
        for (int j = 1; j < SS; j++) lmin = fminf(lmin, vol[j]);
        if (py == 0) sg[i] = lmin;
    }
    __syncthreads();

    // ---- second-level min over 21 rows (warp 0) ----
    if (t < 32) {
        float v = (t < SS) ? sg[t] : 1e30f;
        #pragma unroll
        for (int o = 16; o; o >>= 1)
            v = fminf(v, __shfl_xor_sync(0xffffffffu, v, o));
        if (t == 0) s_min = v;
    }
    __syncthreads();

    // ---- Phase 3: fused weights + accumulation, row reloaded via asm LDS ----
    if (act) {
        // w = exp(-6.25*(vol - vmin)) = 2^(K*vol + M), K = -6.25*log2(e)
        const float K = -9.016844005555897f;
        const float M = -K * s_min;
        float lsum = 0.0f;
        float acc0 = 0.f, acc1 = 0.f, acc2 = 0.f, acc3 = 0.f;
        float r[TILE];
        #pragma unroll
        for (int g = 0; g < 6; g++) {
            // volatile: force reload, don't resurrect phase-1 copies
            asm volatile("ld.shared.v4.f32 {%0,%1,%2,%3}, [%4];"
                : "=f"(r[4*g]), "=f"(r[4*g+1]), "=f"(r[4*g+2]), "=f"(r[4*g+3])
                : "r"(sb + 16u * g));
            if (g >= 1) {
                #pragma unroll
                for (int jj = 0; jj < 4; jj++) {
                    int j = 4 * (g - 1) + jj;
                    float e = fmaf(vol[j], K, M);
                    float wv;
                    asm("ex2.approx.ftz.f32 %0, %1;" : "=f"(wv) : "f"(e));
                    lsum += wv;
                    acc0 = fmaf(wv, r[j],     acc0);
                    acc1 = fmaf(wv, r[j + 1], acc1);
                    acc2 = fmaf(wv, r[j + 2], acc2);
                    acc3 = fmaf(wv, r[j + 3], acc3);
                }
            }
        }
        {
            float e = fmaf(vol[20], K, M);
            float wv;
            asm("ex2.approx.ftz.f32 %0, %1;" : "=f"(wv) : "f"(e));
            lsum += wv;
            acc0 = fmaf(wv, r[20], acc0);
            acc1 = fmaf(wv, r[21], acc1);
            acc2 = fmaf(wv, r[22], acc2);
            acc3 = fmaf(wv, r[23], acc3);
        }
        if (py == 0) sg[i] = lsum;
        red[py * 4 + 0][i] = acc0;
        red[py * 4 + 1][i] = acc1;
        red[py * 4 + 2][i] = acc2;
        red[py * 4 + 3][i] = acc3;
    }
    __syncthreads();

    // ---- Phase 4: reduce over 21 shift-rows, normalize, store ----
    if (t < 16) {
        float s = 0.0f;
        #pragma unroll
        for (int q = 0; q < SS; q++) s += red[t][q];
        float ws = 0.0f;
        #pragma unroll
        for (int q = 0; q < SS; q++) ws += sg[q];
        int py2 = t >> 2, px2 = t & 3;
        out[b * H * W + (by * BS + py2) * W + bx * BS + px2] = s / ws;
    }
}

extern "C" void kernel_launch(void* const* d_in, const int* in_sizes, int n_in,
                              void* d_out, int out_size) {
    const float* im1 = (const float*)d_in[0];
    const float* im2 = (const float*)d_in[1];
    float* out = (float*)d_out;
    dim3 grid(W / BS, H / BS, 2);   // (64, 64, 2)
    pred_kernel<<<grid, 96>>>(im1, im2, out);
}

// round 9
// speedup vs baseline: 1.7703x; 1.1047x over previous
#include <cuda_runtime.h>

#define SS   21      // search size
#define PAD  10
#define BS   4       // block size
#define TILE 24      // BS + SS - 1
#define TP   28      // tile pitch in floats
#define H    256
#define W    256

__global__ __launch_bounds__(96, 16)
void pred_kernel(const float* __restrict__ im1,
                 const float* __restrict__ im2,
                 float* __restrict__ out)
{
    __shared__ __align__(16) float im2t[TILE * TP];
    __shared__ float im1t[16];
    __shared__ float red[16][21];   // per-pixel partial weighted sums over i
    __shared__ float sg[21];        // per-i group weight-sum (phase 3)
    __shared__ int   sg3[3];        // per-warp vol-min (ordered int bits)

    const int t  = threadIdx.x;
    const int bx = blockIdx.x, by = blockIdx.y, b = blockIdx.z;
    const float* i1 = im1 + b * H * W;
    const float* i2 = im2 + b * H * W;

    const int x0 = bx * BS - PAD;
    const int y0 = by * BS - PAD;

    // ---- Phase 0: load 24x24 im2 halo tile ----
    if (bx >= 3 && bx <= 60 && by >= 3 && by <= 60) {
        const int row = t / 12;          // 0..7
        const int c2  = t - row * 12;    // 0..11
        #pragma unroll
        for (int p = 0; p < 3; p++) {
            int r = row + p * 8;
            float2 v = *(const float2*)(i2 + (y0 + r) * W + x0 + c2 * 2);
            *(float2*)&im2t[r * TP + c2 * 2] = v;
        }
    } else {
        #pragma unroll
        for (int q = 0; q < 6; q++) {
            int idx = t + q * 96;
            int r = idx / TILE, c = idx - r * TILE;
            int y = y0 + r, x = x0 + c;
            float v = 0.0f;
            if ((unsigned)y < (unsigned)H && (unsigned)x < (unsigned)W)
                v = i2[y * W + x];
            im2t[r * TP + c] = v;
        }
    }
    if (t < 16) {
        int py = t >> 2, px = t & 3;
        im1t[t] = i1[(by * BS + py) * W + bx * BS + px];
    }
    __syncthreads();

    // ---- mapping: t = 4*i + py (py in adjacent lanes) ----
    const int i  = t >> 2;          // shift row 0..20
    const int py = t & 3;           // pixel row 0..3
    const bool act = (t < 84);
    const unsigned gmask = (t >= 64) ? 0x000FFFFFu : 0xFFFFFFFFu;

    const unsigned sb = (unsigned)__cvta_generic_to_shared(&im2t[(py + i) * TP]);
    float vol[SS];

    // ---- Phase 1: SADs with sliding-window row loads ----
    if (act) {
        const float a0 = im1t[py * 4 + 0], a1 = im1t[py * 4 + 1];
        const float a2 = im1t[py * 4 + 2], a3 = im1t[py * 4 + 3];
        float r[TILE];
        #pragma unroll
        for (int g = 0; g < 6; g++) {
            float4 v = ((const float4*)__cvta_shared_to_generic((size_t)sb))[g];
            r[4*g] = v.x; r[4*g+1] = v.y; r[4*g+2] = v.z; r[4*g+3] = v.w;
            if (g >= 1) {
                #pragma unroll
                for (int jj = 0; jj < 4; jj++) {
                    int j = 4 * (g - 1) + jj;
                    vol[j] = fabsf(a0 - r[j])     + fabsf(a1 - r[j + 1])
                           + fabsf(a2 - r[j + 2]) + fabsf(a3 - r[j + 3]);
                }
            }
        }
        vol[20] = fabsf(a0 - r[20]) + fabsf(a1 - r[21])
                + fabsf(a2 - r[22]) + fabsf(a3 - r[23]);

        // allreduce over py within 4-lane group
        #pragma unroll
        for (int j = 0; j < SS; j++) {
            vol[j] += __shfl_xor_sync(gmask, vol[j], 1);
            vol[j] += __shfl_xor_sync(gmask, vol[j], 2);
        }
        // per-thread min over j (all 4 lanes of a group end identical)
        float lmin = vol[0];
        #pragma unroll
        for (int j = 1; j < SS; j++) lmin = fminf(lmin, vol[j]);
        // warp-wide min in one REDUX (vol >= 0 => s32 order == f32 order)
        int wmin = __reduce_min_sync(gmask, __float_as_int(lmin));
        if ((t & 31) == 0) sg3[t >> 5] = wmin;
    }
    __syncthreads();

    // ---- Phase 3: fused weights + accumulation, row reloaded via asm LDS ----
    if (act) {
        const float vmin = fminf(fminf(__int_as_float(sg3[0]),
                                       __int_as_float(sg3[1])),
                                 __int_as_float(sg3[2]));
        // w = exp(-6.25*(vol - vmin)) = 2^(K*vol + M), K = -6.25*log2(e)
        const float K = -9.016844005555897f;
        const float M = -K * vmin;
        float lsum = 0.0f;
        float acc0 = 0.f, acc1 = 0.f, acc2 = 0.f, acc3 = 0.f;
        float r[TILE];
        #pragma unroll
        for (int g = 0; g < 6; g++) {
            // volatile: force reload, don't resurrect phase-1 copies
            asm volatile("ld.shared.v4.f32 {%0,%1,%2,%3}, [%4];"
                : "=f"(r[4*g]), "=f"(r[4*g+1]), "=f"(r[4*g+2]), "=f"(r[4*g+3])
                : "r"(sb + 16u * g));
            if (g >= 1) {
                #pragma unroll
                for (int jj = 0; jj < 4; jj++) {
                    int j = 4 * (g - 1) + jj;
                    float e = fmaf(vol[j], K, M);
                    float wv;
                    asm("ex2.approx.ftz.f32 %0, %1;" : "=f"(wv) : "f"(e));
                    lsum += wv;
                    acc0 = fmaf(wv, r[j],     acc0);
                    acc1 = fmaf(wv, r[j + 1], acc1);
                    acc2 = fmaf(wv, r[j + 2], acc2);
                    acc3 = fmaf(wv, r[j + 3], acc3);
                }
            }
        }
        {
            float e = fmaf(vol[20], K, M);
            float wv;
            asm("ex2.approx.ftz.f32 %0, %1;" : "=f"(wv) : "f"(e));
            lsum += wv;
            acc0 = fmaf(wv, r[20], acc0);
            acc1 = fmaf(wv, r[21], acc1);
            acc2 = fmaf(wv, r[22], acc2);
            acc3 = fmaf(wv, r[23], acc3);
        }
        if (py == 0) sg[i] = lsum;
        red[py * 4 + 0][i] = acc0;
        red[py * 4 + 1][i] = acc1;
        red[py * 4 + 2][i] = acc2;
        red[py * 4 + 3][i] = acc3;
    }
    __syncthreads();

    // ---- Phase 4: reduce over 21 shift-rows, normalize, store ----
    if (t < 16) {
        float s = 0.0f;
        #pragma unroll
        for (int q = 0; q < SS; q++) s += red[t][q];
        float ws = 0.0f;
        #pragma unroll
        for (int q = 0; q < SS; q++) ws += sg[q];
        int py2 = t >> 2, px2 = t & 3;
        out[b * H * W + (by * BS + py2) * W + bx * BS + px2] = s / ws;
    }
}

extern "C" void kernel_launch(void* const* d_in, const int* in_sizes, int n_in,
                              void* d_out, int out_size) {
    const float* im1 = (const float*)d_in[0];
    const float* im2 = (const float*)d_in[1];
    float* out = (float*)d_out;
    dim3 grid(W / BS, H / BS, 2);   // (64, 64, 2)
    pred_kernel<<<grid, 96>>>(im1, im2, out);
}

// round 10
// speedup vs baseline: 1.9589x; 1.1065x over previous
#include <cuda_runtime.h>

#define SS   21      // search size
#define PAD  10
#define BS   4       // block size
#define TILE 24      // rows: BS + SS - 1
#define TC   28      // tile cols: 2*BS + SS - 1 (pitch)
#define H    256
#define W    256

__global__ __launch_bounds__(96, 13)
void pred_kernel(const float* __restrict__ im1,
                 const float* __restrict__ im2,
                 float* __restrict__ out)
{
    __shared__ __align__(16) float im2t[TILE * TC];   // 24 x 28
    __shared__ float im1t[32];          // 2 sub-blocks x 16
    __shared__ float red[2][16][21];    // [sub][pixel][i] partial weighted sums
    __shared__ float sg[2][21];         // [sub][i] weight-sums
    __shared__ int   sgm[4];            // per-(warp,sub) vol-min (ordered int bits)

    const int t  = threadIdx.x;
    const int bx = blockIdx.x, by = blockIdx.y, b = blockIdx.z;
    const float* i1 = im1 + b * H * W;
    const float* i2 = im2 + b * H * W;

    const int x0 = bx * (2 * BS) - PAD;   // even
    const int y0 = by * BS - PAD;

    // ---- Phase 0: load 24x28 im2 halo tile (shared by both sub-blocks) ----
    if (bx >= 2 && bx <= 29 && by >= 3 && by <= 60) {
        // interior: coalesced float2 (x0 even). 336 float2 over 96 threads.
        #pragma unroll
        for (int p = 0; p < 4; p++) {
            int idx = t + p * 96;
            if (idx < TILE * (TC / 2)) {
                int r  = idx / (TC / 2);
                int c2 = idx - r * (TC / 2);
                float2 v = *(const float2*)(i2 + (y0 + r) * W + x0 + c2 * 2);
                *(float2*)&im2t[r * TC + c2 * 2] = v;
            }
        }
    } else {
        // border: predicated zero-pad
        #pragma unroll
        for (int q = 0; q < 7; q++) {
            int idx = t + q * 96;
            if (idx < TILE * TC) {
                int r = idx / TC, c = idx - r * TC;
                int y = y0 + r, x = x0 + c;
                float v = 0.0f;
                if ((unsigned)y < (unsigned)H && (unsigned)x < (unsigned)W)
                    v = i2[y * W + x];
                im2t[r * TC + c] = v;
            }
        }
    }
    if (t < 32) {
        int s = t >> 4, w16 = t & 15;
        int py = w16 >> 2, px = w16 & 3;
        im1t[t] = i1[(by * BS + py) * W + bx * (2 * BS) + s * BS + px];
    }
    __syncthreads();

    // ---- mapping: s = sub-block (t/48), u = t%48, i = u>>1, h = u&1 ----
    // lane handles pixel rows {2h, 2h+1}; pair (2i,2i+1) reduces over h.
    const int s  = t / 48;
    const int u  = t - s * 48;
    const int i  = u >> 1;            // shift row 0..20
    const int h  = u & 1;             // row-pair selector
    const bool act = (u < 42);
    const int lane = t & 31, wid = t >> 5;
    const unsigned pmask = 3u << (lane & ~1);   // shuffle pair mask

    // tile rows for this lane: ra = 2h + i, rb = ra + 1; col base = s*4 (16B aligned)
    const unsigned sbA = (unsigned)__cvta_generic_to_shared(
                             &im2t[(2 * h + i) * TC + s * BS]);
    const unsigned sbB = sbA + TC * 4u;   // next row

    float vol[SS];

    // ---- Phase 1: 2-row SADs with sliding-window loads, pair-reduce, min ----
    if (act) {
        const float* ap = &im1t[s * 16 + 2 * h * 4];
        const float a0 = ap[0], a1 = ap[1], a2 = ap[2], a3 = ap[3];
        const float b0 = ap[4], b1 = ap[5], b2 = ap[6], b3 = ap[7];
        float rA[TILE], rB[TILE];
        #pragma unroll
        for (int g = 0; g < 6; g++) {
            float4 va = ((const float4*)__cvta_shared_to_generic((size_t)sbA))[g];
            float4 vb = ((const float4*)__cvta_shared_to_generic((size_t)sbB))[g];
            rA[4*g] = va.x; rA[4*g+1] = va.y; rA[4*g+2] = va.z; rA[4*g+3] = va.w;
            rB[4*g] = vb.x; rB[4*g+1] = vb.y; rB[4*g+2] = vb.z; rB[4*g+3] = vb.w;
            if (g >= 1) {
                #pragma unroll
                for (int jj = 0; jj < 4; jj++) {
                    int j = 4 * (g - 1) + jj;
                    vol[j] = fabsf(a0 - rA[j])     + fabsf(a1 - rA[j + 1])
                           + fabsf(a2 - rA[j + 2]) + fabsf(a3 - rA[j + 3])
                           + fabsf(b0 - rB[j])     + fabsf(b1 - rB[j + 1])
                           + fabsf(b2 - rB[j + 2]) + fabsf(b3 - rB[j + 3]);
                }
            }
        }
        vol[20] = fabsf(a0 - rA[20]) + fabsf(a1 - rA[21])
                + fabsf(a2 - rA[22]) + fabsf(a3 - rA[23])
                + fabsf(b0 - rB[20]) + fabsf(b1 - rB[21])
                + fabsf(b2 - rB[22]) + fabsf(b3 - rB[23]);

        // single-step pair allreduce over h
        #pragma unroll
        for (int j = 0; j < SS; j++)
            vol[j] += __shfl_xor_sync(pmask, vol[j], 1);

        // per-thread min, then per-(warp,sub) REDUX min (vol>=0 => s32 order ok)
        float lmin = vol[0];
        #pragma unroll
        for (int j = 1; j < SS; j++) lmin = fminf(lmin, vol[j]);

        unsigned rmask; int slot; bool lead;
        if (wid == 0)            { rmask = 0xFFFFFFFFu; slot = 0; lead = (lane == 0); }
        else if (wid == 1) {
            if (lane < 16)       { rmask = 0x000003FFu; slot = 1; lead = (lane == 0); }
            else                 { rmask = 0xFFFF0000u; slot = 2; lead = (lane == 16); }
        } else                   { rmask = 0x03FFFFFFu; slot = 3; lead = (lane == 0); }
        int wmin = __reduce_min_sync(rmask, __float_as_int(lmin));
        if (lead) sgm[slot] = wmin;
    }
    __syncthreads();

    // ---- Phase 3: fused weights + 2-row accumulation (rows reloaded) ----
    if (act) {
        const float vmin = fminf(__int_as_float(sgm[2 * s]),
                                 __int_as_float(sgm[2 * s + 1]));
        // w = exp(-6.25*(vol - vmin)) = 2^(K*vol + M), K = -6.25*log2(e)
        const float K = -9.016844005555897f;
        const float M = -K * vmin;
        float lsum = 0.0f;
        float c0 = 0.f, c1 = 0.f, c2 = 0.f, c3 = 0.f;   // pixel row 2h
        float d0 = 0.f, d1 = 0.f, d2 = 0.f, d3 = 0.f;   // pixel row 2h+1
        float rA[TILE], rB[TILE];
        #pragma unroll
        for (int g = 0; g < 6; g++) {
            asm volatile("ld.shared.v4.f32 {%0,%1,%2,%3}, [%4];"
                : "=f"(rA[4*g]), "=f"(rA[4*g+1]), "=f"(rA[4*g+2]), "=f"(rA[4*g+3])
                : "r"(sbA + 16u * g));
            asm volatile("ld.shared.v4.f32 {%0,%1,%2,%3}, [%4];"
                : "=f"(rB[4*g]), "=f"(rB[4*g+1]), "=f"(rB[4*g+2]), "=f"(rB[4*g+3])
                : "r"(sbB + 16u * g));
            if (g >= 1) {
                #pragma unroll
                for (int jj = 0; jj < 4; jj++) {
                    int j = 4 * (g - 1) + jj;
                    float e = fmaf(vol[j], K, M);
                    float wv;
                    asm("ex2.approx.ftz.f32 %0, %1;" : "=f"(wv) : "f"(e));
                    lsum += wv;
                    c0 = fmaf(wv, rA[j],     c0);
                    c1 = fmaf(wv, rA[j + 1], c1);
                    c2 = fmaf(wv, rA[j + 2], c2);
                    c3 = fmaf(wv, rA[j + 3], c3);
                    d0 = fmaf(wv, rB[j],     d0);
                    d1 = fmaf(wv, rB[j + 1], d1);
                    d2 = fmaf(wv, rB[j + 2], d2);
                    d3 = fmaf(wv, rB[j + 3], d3);
                }
            }
        }
        {
            float e = fmaf(vol[20], K, M);
            float wv;
            asm("ex2.approx.ftz.f32 %0, %1;" : "=f"(wv) : "f"(e));
            lsum += wv;
            c0 = fmaf(wv, rA[20], c0); c1 = fmaf(wv, rA[21], c1);
            c2 = fmaf(wv, rA[22], c2); c3 = fmaf(wv, rA[23], c3);
            d0 = fmaf(wv, rB[20], d0); d1 = fmaf(wv, rB[21], d1);
            d2 = fmaf(wv, rB[22], d2); d3 = fmaf(wv, rB[23], d3);
        }
        if (h == 0) sg[s][i] = lsum;     // pair lanes hold identical lsum
        const int pr = 2 * h * 4;
        red[s][pr + 0][i] = c0;  red[s][pr + 1][i] = c1;
        red[s][pr + 2][i] = c2;  red[s][pr + 3][i] = c3;
        red[s][pr + 4][i] = d0;  red[s][pr + 5][i] = d1;
        red[s][pr + 6][i] = d2;  red[s][pr + 7][i] = d3;
    }
    __syncthreads();

    // ---- Phase 4: reduce over 21 shift-rows, normalize, store ----
    if (t < 32) {
        int so = t >> 4, tt = t & 15;
        float sum = 0.0f;
        #pragma unroll
        for (int q = 0; q < SS; q++) sum += red[so][tt][q];
        float ws = 0.0f;
        #pragma unroll
        for (int q = 0; q < SS; q++) ws += sg[so][q];
        int py2 = tt >> 2, px2 = tt & 3;
        out[b * H * W + (by * BS + py2) * W + bx * (2 * BS) + so * BS + px2]
            = sum / ws;
    }
}

extern "C" void kernel_launch(void* const* d_in, const int* in_sizes, int n_in,
                              void* d_out, int out_size) {
    const float* im1 = (const float*)d_in[0];
    const float* im2 = (const float*)d_in[1];
    float* out = (float*)d_out;
    dim3 grid(W / (2 * BS), H / BS, 2);   // (32, 64, 2)
    pred_kernel<<<grid, 96>>>(im1, im2, out);
}